// round 16
// baseline (speedup 1.0000x reference)
#include <cuda_runtime.h>
#include <cuda_bf16.h>
#include <cstdint>

namespace {
constexpr int B  = 8;
constexpr int S  = 1024;
constexpr int H  = 1024;
constexpr int NH = 16;
constexpr int HD = 64;
constexpr int M  = B * S;    // 8192
constexpr int BH = B * NH;   // 128
constexpr float SCALE  = 0.125f;
constexpr float LN_EPS = 1e-12f;

// bf16 GEMM smem (u16 units): 3 stages x (A 128x40 + B 128x40), 128-thr CTA
constexpr int GA   = 128 * 40;          // 5120 u16
constexpr int GSTG = 2 * GA;            // 10240 u16 per stage
constexpr int GEMM_SMEM = 3 * GSTG * 2; // 61440 bytes

// flash smem (u16 units, stride 72): Q,K,V bf16 + mask
constexpr int FROW = 72;
constexpr int FQ = 0;
constexpr int FK = 128 * FROW;
constexpr int FV = 2 * 128 * FROW;
constexpr int FMASK_BY = 3 * 128 * FROW * 2;   // 55296
constexpr int FLASH_SMEM = FMASK_BY + 512;     // 55808
}

// ---------------------------------------------------------------------------
// Scratch (allocation-free: __device__ globals)
// ---------------------------------------------------------------------------
__device__ __nv_bfloat16 g_hb[M * H];
__device__ __nv_bfloat16 g_wb[4u * H * H];
__device__ __nv_bfloat16 g_qb[BH * S * HD];
__device__ __nv_bfloat16 g_kb[BH * S * HD];
__device__ __nv_bfloat16 g_vb[BH * S * HD];
__device__ __nv_bfloat16 g_cb[M * H];
__device__ float g_proj[M * H];

// ---------------------------------------------------------------------------
// helpers
// ---------------------------------------------------------------------------
__device__ __forceinline__ uint32_t smem_u32(const void* p) {
    uint32_t a;
    asm("{ .reg .u64 t; cvta.to.shared.u64 t, %1; cvt.u32.u64 %0, t; }"
        : "=r"(a) : "l"(p));
    return a;
}
__device__ __forceinline__ void mma_bf16(float* c, const uint32_t* a, const uint32_t* b) {
    asm volatile(
        "mma.sync.aligned.m16n8k16.row.col.f32.bf16.bf16.f32 "
        "{%0,%1,%2,%3}, {%4,%5,%6,%7}, {%8,%9}, {%0,%1,%2,%3};"
        : "+f"(c[0]), "+f"(c[1]), "+f"(c[2]), "+f"(c[3])
        : "r"(a[0]), "r"(a[1]), "r"(a[2]), "r"(a[3]), "r"(b[0]), "r"(b[1]));
}
__device__ __forceinline__ void ldm_x4(uint32_t* r, uint32_t addr) {
    asm volatile("ldmatrix.sync.aligned.m8n8.x4.shared.b16 {%0,%1,%2,%3}, [%4];"
                 : "=r"(r[0]), "=r"(r[1]), "=r"(r[2]), "=r"(r[3]) : "r"(addr));
}
__device__ __forceinline__ void ldm_x4t(uint32_t* r, uint32_t addr) {
    asm volatile("ldmatrix.sync.aligned.m8n8.x4.trans.shared.b16 {%0,%1,%2,%3}, [%4];"
                 : "=r"(r[0]), "=r"(r[1]), "=r"(r[2]), "=r"(r[3]) : "r"(addr));
}
__device__ __forceinline__ uint32_t cvt2(float x, float y) {
    uint32_t h;
    asm("cvt.rn.bf16x2.f32 %0, %1, %2;" : "=r"(h) : "f"(y), "f"(x));
    return h;
}
__device__ __forceinline__ void cpa16(uint32_t s, const void* g) {
    asm volatile("cp.async.cg.shared.global [%0], [%1], 16;" :: "r"(s), "l"(g));
}
#define CP_COMMIT() asm volatile("cp.async.commit_group;" ::: "memory")
#define CP_WAIT0()  asm volatile("cp.async.wait_group 0;" ::: "memory")
#define CP_WAIT1()  asm volatile("cp.async.wait_group 1;" ::: "memory")

// ---------------------------------------------------------------------------
// One-pass fp32 -> bf16 of hidden + all 4 weights.
// ---------------------------------------------------------------------------
__global__ __launch_bounds__(256, 8)
void cvt_all(const float* __restrict__ h,  const float* __restrict__ wq,
             const float* __restrict__ wk, const float* __restrict__ wv,
             const float* __restrict__ wo)
{
    const size_t i = ((size_t)blockIdx.x * 256 + threadIdx.x) * 4;
    const float* src;
    __nv_bfloat16* dst;
    size_t off;
    if (i < (size_t)M * H) {
        src = h; dst = g_hb; off = i;
    } else {
        const size_t j = i - (size_t)M * H;
        const int ws = (int)(j >> 20);
        off = j & 0xFFFFFu;
        src = (ws == 0) ? wq : (ws == 1) ? wk : (ws == 2) ? wv : wo;
        dst = g_wb + ((size_t)ws << 20);
    }
    float4 f = *(const float4*)&src[off];
    uint2 o;
    o.x = cvt2(f.x, f.y);
    o.y = cvt2(f.z, f.w);
    *(uint2*)&dst[off] = o;
}

// ---------------------------------------------------------------------------
// bf16 single-pass GEMM: C = X @ W^T + bias. 128x128 tile, 128 thr,
// 4 warps as 2(m) x 2(n) of 64x64, TWO CTAs per SM, 3-stage cp.async.
// dst_sel < 0: fused QKV via blockIdx.z -> q/k/v bf16 headsplit.
// dst_sel == 3: g_proj fp32 (X := g_cb).
// ---------------------------------------------------------------------------
__global__ __launch_bounds__(128, 2)
void gemm_bf16s(const float* __restrict__ b0, const float* __restrict__ b1,
                const float* __restrict__ b2, int dst_sel)
{
    extern __shared__ __align__(16) uint16_t gsm[];

    const int ds = (dst_sel < 0) ? (int)blockIdx.z : dst_sel;
    const bool headsplit = ds < 3;
    const float* bias = (ds == 1) ? b1 : (ds == 2) ? b2 : b0;
    const __nv_bfloat16* X = headsplit ? g_hb : g_cb;
    const __nv_bfloat16* W = g_wb + (size_t)ds * H * H;
    __nv_bfloat16* dqkv = (ds == 0) ? g_qb : (ds == 1) ? g_kb : g_vb;

    const int tid  = threadIdx.x;
    const int lane = tid & 31;
    const int wid  = tid >> 5;           // 0..3
    const int bm   = blockIdx.y * 128;
    const int bn   = blockIdx.x * 128;
    const int m_off = (wid & 1) * 64;
    const int n_off = (wid >> 1) * 64;

    // cp.async loaders: 1 thread per row for A and B (32 halves = 4 x 16B)
    const __nv_bfloat16* xa = X + (size_t)(bm + tid) * H;
    const __nv_bfloat16* wb = W + (size_t)(bn + tid) * H;
    const uint32_t smb = smem_u32(gsm);

    auto issue = [&](int s, int st) {
        const uint32_t base = smb + (uint32_t)(st * GSTG) * 2;
        const __nv_bfloat16* xp = xa + s * 32;
        const uint32_t da = base + (uint32_t)(tid * 40) * 2;
        cpa16(da,      xp);
        cpa16(da + 16, xp + 8);
        cpa16(da + 32, xp + 16);
        cpa16(da + 48, xp + 24);
        const __nv_bfloat16* wp = wb + s * 32;
        const uint32_t db = base + (uint32_t)(GA + tid * 40) * 2;
        cpa16(db,      wp);
        cpa16(db + 16, wp + 8);
        cpa16(db + 32, wp + 16);
        cpa16(db + 48, wp + 24);
        CP_COMMIT();
    };

    float acc[4][8][4];
#pragma unroll
    for (int i = 0; i < 4; i++)
#pragma unroll
        for (int j = 0; j < 8; j++)
#pragma unroll
            for (int t = 0; t < 4; t++) acc[i][j][t] = 0.f;

    issue(0, 0);
    issue(1, 1);

    const int NS = H / 32;  // 32 slabs
    int st = 0;
    for (int s = 0; s < NS; s++) {
        if (s + 2 < NS) { CP_WAIT1(); } else { CP_WAIT0(); }
        __syncthreads();
        if (s + 2 < NS) {
            int st2 = st + 2; if (st2 >= 3) st2 -= 3;
            issue(s + 2, st2);
        }

        const uint16_t* sA = gsm + st * GSTG;
        const uint16_t* sB = sA + GA;

#pragma unroll
        for (int kk = 0; kk < 2; kk++) {
            uint32_t a[4][4], b[4][4];
            const int arow = m_off + (lane & 15);
            const int acol = kk * 16 + (lane >> 4) * 8;
#pragma unroll
            for (int mi = 0; mi < 4; mi++)
                ldm_x4(a[mi], smem_u32(&sA[(arow + mi * 16) * 40 + acol]));
            const int brow = n_off + (lane & 7) + ((lane >> 4) & 1) * 8;
            const int bcol = kk * 16 + ((lane >> 3) & 1) * 8;
#pragma unroll
            for (int g = 0; g < 4; g++)
                ldm_x4(b[g], smem_u32(&sB[(brow + g * 16) * 40 + bcol]));
#pragma unroll
            for (int mi = 0; mi < 4; mi++)
#pragma unroll
                for (int g = 0; g < 4; g++)
#pragma unroll
                    for (int hh = 0; hh < 2; hh++)
                        mma_bf16(acc[mi][g * 2 + hh], a[mi], &b[g][hh * 2]);
        }
        if (++st == 3) st = 0;
    }

#pragma unroll
    for (int mi = 0; mi < 4; mi++) {
#pragma unroll
        for (int ni = 0; ni < 8; ni++) {
            const int col = bn + n_off + ni * 8 + (lane & 3) * 2;
            const float2 bs = *(const float2*)&bias[col];
#pragma unroll
            for (int h2 = 0; h2 < 2; h2++) {
                const int row = bm + m_off + mi * 16 + (lane >> 2) + h2 * 8;
                float vx = acc[mi][ni][h2 * 2 + 0] + bs.x;
                float vy = acc[mi][ni][h2 * 2 + 1] + bs.y;
                if (headsplit) {
                    const int b_ = row >> 10, s_ = row & 1023;
                    const int h_ = col >> 6,  d_ = col & 63;
                    const size_t idx = ((size_t)(b_ * NH + h_) * S + s_) * HD + d_;
                    *(uint32_t*)&dqkv[idx] = cvt2(vx, vy);
                } else {
                    float2 v; v.x = vx; v.y = vy;
                    *(float2*)&g_proj[(size_t)row * H + col] = v;
                }
            }
        }
    }
}

// ---------------------------------------------------------------------------
// Flash attention: bf16 single-pass QK^T and PV. Block = (q-tile 128, head).
// ---------------------------------------------------------------------------
__global__ __launch_bounds__(256, 1)
void flash_attn(const float* __restrict__ mask)
{
    extern __shared__ __align__(16) char fsm[];
    uint16_t* sQ = (uint16_t*)fsm + FQ;
    uint16_t* sK = (uint16_t*)fsm + FK;
    uint16_t* sV = (uint16_t*)fsm + FV;
    float* maskS = (float*)(fsm + FMASK_BY);

    const int head = blockIdx.y;
    const int b_   = head >> 4;
    const int h_   = head & 15;
    const size_t hbase = (size_t)head * S * HD;
    const float* mrow = mask + (size_t)b_ * S;

    const int tid  = threadIdx.x;
    const int lane = tid & 31;
    const int w    = tid >> 5;
    const int bq   = blockIdx.x * 128;

    const int lr = tid >> 1;
    const int lk = (tid & 1) * 32;

    {
        const uint4* qg = (const uint4*)(g_qb + hbase + (size_t)(bq + lr) * HD + lk);
        uint4* dq = (uint4*)&sQ[lr * FROW + lk];
#pragma unroll
        for (int q = 0; q < 4; q++) dq[q] = qg[q];
    }
    __syncthreads();

    uint32_t qa[4][4];
    {
        const int ar = w * 16 + (lane & 15);
        const int acb = (lane >> 4) * 8;
#pragma unroll
        for (int kk = 0; kk < 4; kk++)
            ldm_x4(qa[kk], smem_u32(&sQ[ar * FROW + kk * 16 + acb]));
    }

    float acco[8][4];
#pragma unroll
    for (int i = 0; i < 8; i++)
#pragma unroll
        for (int t = 0; t < 4; t++) acco[i][t] = 0.f;
    float m0 = -3.4e38f, m1 = -3.4e38f, l0 = 0.f, l1 = 0.f;

    for (int j = 0; j < S / 128; j++) {
        __syncthreads();
        {
            const size_t off = hbase + (size_t)(j * 128 + lr) * HD + lk;
            const uint4* kg = (const uint4*)(g_kb + off);
            const uint4* vg = (const uint4*)(g_vb + off);
            uint4* dk = (uint4*)&sK[lr * FROW + lk];
            uint4* dv = (uint4*)&sV[lr * FROW + lk];
#pragma unroll
            for (int q = 0; q < 4; q++) { dk[q] = kg[q]; dv[q] = vg[q]; }
            if (tid < 128) maskS[tid] = mrow[j * 128 + tid];
        }
        __syncthreads();

        float accs[16][4];
#pragma unroll
        for (int i = 0; i < 16; i++)
#pragma unroll
            for (int t = 0; t < 4; t++) accs[i][t] = 0.f;

#pragma unroll
        for (int kk = 0; kk < 4; kk++) {
            const int krow = (lane & 7) + ((lane >> 4) & 1) * 8;
            const int kcol = kk * 16 + ((lane >> 3) & 1) * 8;
#pragma unroll
            for (int np = 0; np < 8; np++) {
                uint32_t kf[4];
                ldm_x4(kf, smem_u32(&sK[(np * 16 + krow) * FROW + kcol]));
                mma_bf16(accs[2*np],   qa[kk], &kf[0]);
                mma_bf16(accs[2*np+1], qa[kk], &kf[2]);
            }
        }

        float tmax0 = -3.4e38f, tmax1 = -3.4e38f;
#pragma unroll
        for (int ni = 0; ni < 16; ni++) {
            const int c = ni * 8 + (lane & 3) * 2;
            const float mk0 = maskS[c], mk1 = maskS[c + 1];
            accs[ni][0] = fmaf(accs[ni][0], SCALE, mk0);
            accs[ni][1] = fmaf(accs[ni][1], SCALE, mk1);
            accs[ni][2] = fmaf(accs[ni][2], SCALE, mk0);
            accs[ni][3] = fmaf(accs[ni][3], SCALE, mk1);
            tmax0 = fmaxf(tmax0, fmaxf(accs[ni][0], accs[ni][1]));
            tmax1 = fmaxf(tmax1, fmaxf(accs[ni][2], accs[ni][3]));
        }
        tmax0 = fmaxf(tmax0, __shfl_xor_sync(~0u, tmax0, 1));
        tmax0 = fmaxf(tmax0, __shfl_xor_sync(~0u, tmax0, 2));
        tmax1 = fmaxf(tmax1, __shfl_xor_sync(~0u, tmax1, 1));
        tmax1 = fmaxf(tmax1, __shfl_xor_sync(~0u, tmax1, 2));

        const float mn0 = fmaxf(m0, tmax0);
        const float mn1 = fmaxf(m1, tmax1);
        const float alpha0 = __expf(m0 - mn0);
        const float alpha1 = __expf(m1 - mn1);
        m0 = mn0; m1 = mn1;

        float sum0 = 0.f, sum1 = 0.f;
#pragma unroll
        for (int ni = 0; ni < 16; ni++) {
            accs[ni][0] = __expf(accs[ni][0] - mn0);
            accs[ni][1] = __expf(accs[ni][1] - mn0);
            accs[ni][2] = __expf(accs[ni][2] - mn1);
            accs[ni][3] = __expf(accs[ni][3] - mn1);
            sum0 += accs[ni][0] + accs[ni][1];
            sum1 += accs[ni][2] + accs[ni][3];
        }
        sum0 += __shfl_xor_sync(~0u, sum0, 1);
        sum0 += __shfl_xor_sync(~0u, sum0, 2);
        sum1 += __shfl_xor_sync(~0u, sum1, 1);
        sum1 += __shfl_xor_sync(~0u, sum1, 2);
        l0 = l0 * alpha0 + sum0;
        l1 = l1 * alpha1 + sum1;

#pragma unroll
        for (int ni = 0; ni < 8; ni++) {
            acco[ni][0] *= alpha0; acco[ni][1] *= alpha0;
            acco[ni][2] *= alpha1; acco[ni][3] *= alpha1;
        }

#pragma unroll
        for (int kk = 0; kk < 8; kk++) {
            uint32_t ph[4];
            ph[0] = cvt2(accs[2*kk][0],   accs[2*kk][1]);
            ph[1] = cvt2(accs[2*kk][2],   accs[2*kk][3]);
            ph[2] = cvt2(accs[2*kk+1][0], accs[2*kk+1][1]);
            ph[3] = cvt2(accs[2*kk+1][2], accs[2*kk+1][3]);
            const int vrow = kk * 16 + (lane & 7) + ((lane >> 3) & 1) * 8;
#pragma unroll
            for (int np = 0; np < 4; np++) {
                const int vcol = np * 16 + (lane >> 4) * 8;
                uint32_t vh4[4];
                ldm_x4t(vh4, smem_u32(&sV[vrow * FROW + vcol]));
                mma_bf16(acco[2*np],   ph, &vh4[0]);
                mma_bf16(acco[2*np+1], ph, &vh4[2]);
            }
        }
    }

    const float inv0 = 1.f / l0;
    const float inv1 = 1.f / l1;
    const int q0 = bq + w * 16 + (lane >> 2);
#pragma unroll
    for (int ni = 0; ni < 8; ni++) {
        const int d = ni * 8 + (lane & 3) * 2;
        const size_t i0 = ((size_t)(b_ * S + q0)) * H + h_ * HD + d;
        const size_t i1 = ((size_t)(b_ * S + q0 + 8)) * H + h_ * HD + d;
        *(uint32_t*)&g_cb[i0] = cvt2(acco[ni][0] * inv0, acco[ni][1] * inv0);
        *(uint32_t*)&g_cb[i1] = cvt2(acco[ni][2] * inv1, acco[ni][3] * inv1);
    }
}

// ---------------------------------------------------------------------------
// out = LayerNorm(g_proj + hidden) * gamma + beta
// ---------------------------------------------------------------------------
__global__ __launch_bounds__(256, 1)
void add_ln(const float* __restrict__ hidden,
            const float* __restrict__ gamma,
            const float* __restrict__ beta,
            float* __restrict__ out)
{
    const size_t row = blockIdx.x;
    const int tid = threadIdx.x;
    __shared__ float r1[8], r2[8];

    float4 a  = *(const float4*)&g_proj[row * H + tid * 4];
    float4 hv = *(const float4*)&hidden[row * H + tid * 4];
    float x0 = a.x + hv.x, x1 = a.y + hv.y, x2 = a.z + hv.z, x3 = a.w + hv.w;

    float s1 = x0 + x1 + x2 + x3;
    float s2 = fmaf(x0, x0, fmaf(x1, x1, fmaf(x2, x2, x3 * x3)));
#pragma unroll
    for (int o = 16; o; o >>= 1) {
        s1 += __shfl_xor_sync(~0u, s1, o);
        s2 += __shfl_xor_sync(~0u, s2, o);
    }
    if ((tid & 31) == 0) { r1[tid >> 5] = s1; r2[tid >> 5] = s2; }
    __syncthreads();
    float t1 = 0.f, t2 = 0.f;
#pragma unroll
    for (int i = 0; i < 8; i++) { t1 += r1[i]; t2 += r2[i]; }

    const float mu  = t1 * (1.f / H);
    const float var = t2 * (1.f / H) - mu * mu;
    const float inv = rsqrtf(var + LN_EPS);

    float4 g  = *(const float4*)&gamma[tid * 4];
    float4 bt = *(const float4*)&beta[tid * 4];
    float4 o;
    o.x = (x0 - mu) * inv * g.x + bt.x;
    o.y = (x1 - mu) * inv * g.y + bt.y;
    o.z = (x2 - mu) * inv * g.z + bt.z;
    o.w = (x3 - mu) * inv * g.w + bt.w;
    *(float4*)&out[row * H + tid * 4] = o;
}

// ---------------------------------------------------------------------------
extern "C" void kernel_launch(void* const* d_in, const int* in_sizes, int n_in,
                              void* d_out, int out_size)
{
    const float* hidden = (const float*)d_in[0];
    const float* mask   = (const float*)d_in[1];
    const float* Wq     = (const float*)d_in[2];
    const float* bq     = (const float*)d_in[3];
    const float* Wk     = (const float*)d_in[4];
    const float* bk     = (const float*)d_in[5];
    const float* Wv     = (const float*)d_in[6];
    const float* bv     = (const float*)d_in[7];
    const float* Wo     = (const float*)d_in[8];
    const float* bo     = (const float*)d_in[9];
    const float* gamma  = (const float*)d_in[10];
    const float* beta   = (const float*)d_in[11];
    float* out          = (float*)d_out;

    cudaFuncSetAttribute(gemm_bf16s, cudaFuncAttributeMaxDynamicSharedMemorySize,
                         GEMM_SMEM);
    cudaFuncSetAttribute(flash_attn, cudaFuncAttributeMaxDynamicSharedMemorySize,
                         FLASH_SMEM);

    dim3 blk(256);
    cvt_all<<<((size_t)M * H + 4u * H * H) / 1024, blk>>>(hidden, Wq, Wk, Wv, Wo);

    dim3 gqkv(H / 128, M / 128, 3);     // (8, 64, 3) fused QKV
    gemm_bf16s<<<gqkv, 128, GEMM_SMEM>>>(bq, bk, bv, -1);

    dim3 gfa(S / 128, BH);
    flash_attn<<<gfa, blk, FLASH_SMEM>>>(mask);

    dim3 gproj(H / 128, M / 128);       // (8, 64)
    gemm_bf16s<<<gproj, 128, GEMM_SMEM>>>(bo, bo, bo, 3);

    add_ln<<<M, blk>>>(hidden, gamma, beta, out);
}

// round 17
// speedup vs baseline: 1.0080x; 1.0080x over previous
#include <cuda_runtime.h>
#include <cuda_bf16.h>
#include <cstdint>

namespace {
constexpr int B  = 8;
constexpr int S  = 1024;
constexpr int H  = 1024;
constexpr int NH = 16;
constexpr int HD = 64;
constexpr int M  = B * S;    // 8192
constexpr int BH = B * NH;   // 128
constexpr float SCALE  = 0.125f;
constexpr float LN_EPS = 1e-12f;

// bf16 GEMM smem (u16 units): 3 stages x (A 128x40 + B 256x40)
constexpr int GA   = 128 * 40;          // 5120 u16
constexpr int GB   = 256 * 40;          // 10240 u16
constexpr int GSTG = GA + GB;           // 15360 u16 per stage
constexpr int GEMM_SMEM = 3 * GSTG * 2; // 92160 bytes

// flash smem (u16 units, stride 72): Q,K,V bf16 + mask
constexpr int FROW = 72;
constexpr int FQ = 0;
constexpr int FK = 128 * FROW;
constexpr int FV = 2 * 128 * FROW;
constexpr int FMASK_BY = 3 * 128 * FROW * 2;   // 55296
constexpr int FLASH_SMEM = FMASK_BY + 512;     // 55808
}

// ---------------------------------------------------------------------------
// Scratch (allocation-free: __device__ globals)
// ---------------------------------------------------------------------------
__device__ __nv_bfloat16 g_hb[M * H];
__device__ __nv_bfloat16 g_wb[4u * H * H];
__device__ __nv_bfloat16 g_qb[BH * S * HD];
__device__ __nv_bfloat16 g_kb[BH * S * HD];
__device__ __nv_bfloat16 g_vb[BH * S * HD];
__device__ __nv_bfloat16 g_cb[M * H];
__device__ float g_proj[M * H];

// ---------------------------------------------------------------------------
// helpers
// ---------------------------------------------------------------------------
__device__ __forceinline__ uint32_t smem_u32(const void* p) {
    uint32_t a;
    asm("{ .reg .u64 t; cvta.to.shared.u64 t, %1; cvt.u32.u64 %0, t; }"
        : "=r"(a) : "l"(p));
    return a;
}
__device__ __forceinline__ void mma_bf16(float* c, const uint32_t* a, const uint32_t* b) {
    asm volatile(
        "mma.sync.aligned.m16n8k16.row.col.f32.bf16.bf16.f32 "
        "{%0,%1,%2,%3}, {%4,%5,%6,%7}, {%8,%9}, {%0,%1,%2,%3};"
        : "+f"(c[0]), "+f"(c[1]), "+f"(c[2]), "+f"(c[3])
        : "r"(a[0]), "r"(a[1]), "r"(a[2]), "r"(a[3]), "r"(b[0]), "r"(b[1]));
}
__device__ __forceinline__ void ldm_x4(uint32_t* r, uint32_t addr) {
    asm volatile("ldmatrix.sync.aligned.m8n8.x4.shared.b16 {%0,%1,%2,%3}, [%4];"
                 : "=r"(r[0]), "=r"(r[1]), "=r"(r[2]), "=r"(r[3]) : "r"(addr));
}
__device__ __forceinline__ void ldm_x4t(uint32_t* r, uint32_t addr) {
    asm volatile("ldmatrix.sync.aligned.m8n8.x4.trans.shared.b16 {%0,%1,%2,%3}, [%4];"
                 : "=r"(r[0]), "=r"(r[1]), "=r"(r[2]), "=r"(r[3]) : "r"(addr));
}
__device__ __forceinline__ uint32_t cvt2(float x, float y) {
    uint32_t h;
    asm("cvt.rn.bf16x2.f32 %0, %1, %2;" : "=r"(h) : "f"(y), "f"(x));
    return h;
}
__device__ __forceinline__ void cpa16(uint32_t s, const void* g) {
    asm volatile("cp.async.cg.shared.global [%0], [%1], 16;" :: "r"(s), "l"(g));
}
#define CP_COMMIT() asm volatile("cp.async.commit_group;" ::: "memory")
#define CP_WAIT0()  asm volatile("cp.async.wait_group 0;" ::: "memory")
#define CP_WAIT1()  asm volatile("cp.async.wait_group 1;" ::: "memory")

// ---------------------------------------------------------------------------
// One-pass fp32 -> bf16 of hidden + all 4 weights.
// ---------------------------------------------------------------------------
__global__ __launch_bounds__(256, 8)
void cvt_all(const float* __restrict__ h,  const float* __restrict__ wq,
             const float* __restrict__ wk, const float* __restrict__ wv,
             const float* __restrict__ wo)
{
    const size_t i = ((size_t)blockIdx.x * 256 + threadIdx.x) * 4;
    const float* src;
    __nv_bfloat16* dst;
    size_t off;
    if (i < (size_t)M * H) {
        src = h; dst = g_hb; off = i;
    } else {
        const size_t j = i - (size_t)M * H;
        const int ws = (int)(j >> 20);
        off = j & 0xFFFFFu;
        src = (ws == 0) ? wq : (ws == 1) ? wk : (ws == 2) ? wv : wo;
        dst = g_wb + ((size_t)ws << 20);
    }
    float4 f = *(const float4*)&src[off];
    uint2 o;
    o.x = cvt2(f.x, f.y);
    o.y = cvt2(f.z, f.w);
    *(uint2*)&dst[off] = o;
}

// ---------------------------------------------------------------------------
// bf16 single-pass GEMM: C = X @ W^T + bias. 128x256 block, 256 thr,
// 8 warps as 2(m) x 4(n) of 64x64. 3-stage cp.async; both k-steps'
// fragments loaded before the MMA burst (latency exposed once per slab).
// dst_sel < 0: fused QKV via blockIdx.z. dst_sel == 3: g_proj (X := g_cb).
// ---------------------------------------------------------------------------
__global__ __launch_bounds__(256, 1)
void gemm_bf16s(const float* __restrict__ b0, const float* __restrict__ b1,
                const float* __restrict__ b2, int dst_sel)
{
    extern __shared__ __align__(16) uint16_t gsm[];

    const int ds = (dst_sel < 0) ? (int)blockIdx.z : dst_sel;
    const bool headsplit = ds < 3;
    const float* bias = (ds == 1) ? b1 : (ds == 2) ? b2 : b0;
    const __nv_bfloat16* X = headsplit ? g_hb : g_cb;
    const __nv_bfloat16* W = g_wb + (size_t)ds * H * H;
    __nv_bfloat16* dqkv = (ds == 0) ? g_qb : (ds == 1) ? g_kb : g_vb;

    const int tid  = threadIdx.x;
    const int lane = tid & 31;
    const int wid  = tid >> 5;
    const int bm   = blockIdx.y * 128;
    const int bn   = blockIdx.x * 256;
    const int m_off = (wid & 1) * 64;
    const int n_off = (wid >> 1) * 64;

    const int lrA = tid >> 1;
    const int lkA = (tid & 1) * 16;
    const __nv_bfloat16* xa = X + (size_t)(bm + lrA) * H + lkA;
    const __nv_bfloat16* wb = W + (size_t)(bn + tid) * H;
    const uint32_t smb = smem_u32(gsm);

    auto issue = [&](int s, int st) {
        const uint32_t base = smb + (uint32_t)(st * GSTG) * 2;
        const __nv_bfloat16* xp = xa + s * 32;
        const uint32_t da = base + (uint32_t)(lrA * 40 + lkA) * 2;
        cpa16(da,      xp);
        cpa16(da + 16, xp + 8);
        const __nv_bfloat16* wp = wb + s * 32;
        const uint32_t db = base + (uint32_t)(GA + tid * 40) * 2;
        cpa16(db,      wp);
        cpa16(db + 16, wp + 8);
        cpa16(db + 32, wp + 16);
        cpa16(db + 48, wp + 24);
        CP_COMMIT();
    };

    float acc[4][8][4];
#pragma unroll
    for (int i = 0; i < 4; i++)
#pragma unroll
        for (int j = 0; j < 8; j++)
#pragma unroll
            for (int t = 0; t < 4; t++) acc[i][j][t] = 0.f;

    issue(0, 0);
    issue(1, 1);

    const int NS = H / 32;  // 32 slabs
    int st = 0;
    for (int s = 0; s < NS; s++) {
        if (s + 2 < NS) { CP_WAIT1(); } else { CP_WAIT0(); }
        __syncthreads();
        if (s + 2 < NS) {
            int st2 = st + 2; if (st2 >= 3) st2 -= 3;
            issue(s + 2, st2);
        }

        const uint16_t* sA = gsm + st * GSTG;
        const uint16_t* sB = sA + GA;

        // ---- load ALL fragments for both k-steps, then MMA burst ----
        uint32_t a0[4][4], a1[4][4], b0r[4][4], b1r[4][4];
        const int arow = m_off + (lane & 15);
        const int acb  = (lane >> 4) * 8;
        const int brow = n_off + (lane & 7) + ((lane >> 4) & 1) * 8;
        const int bcb  = ((lane >> 3) & 1) * 8;
#pragma unroll
        for (int mi = 0; mi < 4; mi++) {
            ldm_x4(a0[mi], smem_u32(&sA[(arow + mi * 16) * 40 + acb]));
            ldm_x4(a1[mi], smem_u32(&sA[(arow + mi * 16) * 40 + 16 + acb]));
        }
#pragma unroll
        for (int g = 0; g < 4; g++) {
            ldm_x4(b0r[g], smem_u32(&sB[(brow + g * 16) * 40 + bcb]));
            ldm_x4(b1r[g], smem_u32(&sB[(brow + g * 16) * 40 + 16 + bcb]));
        }
#pragma unroll
        for (int mi = 0; mi < 4; mi++)
#pragma unroll
            for (int g = 0; g < 4; g++)
#pragma unroll
                for (int hh = 0; hh < 2; hh++)
                    mma_bf16(acc[mi][g * 2 + hh], a0[mi], &b0r[g][hh * 2]);
#pragma unroll
        for (int mi = 0; mi < 4; mi++)
#pragma unroll
            for (int g = 0; g < 4; g++)
#pragma unroll
                for (int hh = 0; hh < 2; hh++)
                    mma_bf16(acc[mi][g * 2 + hh], a1[mi], &b1r[g][hh * 2]);

        if (++st == 3) st = 0;
    }

#pragma unroll
    for (int mi = 0; mi < 4; mi++) {
#pragma unroll
        for (int ni = 0; ni < 8; ni++) {
            const int col = bn + n_off + ni * 8 + (lane & 3) * 2;
            const float2 bs = *(const float2*)&bias[col];
#pragma unroll
            for (int h2 = 0; h2 < 2; h2++) {
                const int row = bm + m_off + mi * 16 + (lane >> 2) + h2 * 8;
                float vx = acc[mi][ni][h2 * 2 + 0] + bs.x;
                float vy = acc[mi][ni][h2 * 2 + 1] + bs.y;
                if (headsplit) {
                    const int b_ = row >> 10, s_ = row & 1023;
                    const int h_ = col >> 6,  d_ = col & 63;
                    const size_t idx = ((size_t)(b_ * NH + h_) * S + s_) * HD + d_;
                    *(uint32_t*)&dqkv[idx] = cvt2(vx, vy);
                } else {
                    float2 v; v.x = vx; v.y = vy;
                    *(float2*)&g_proj[(size_t)row * H + col] = v;
                }
            }
        }
    }
}

// ---------------------------------------------------------------------------
// Flash attention: bf16 single-pass QK^T and PV, fragment prefetch.
// Block = (q-tile 128, head).
// ---------------------------------------------------------------------------
__global__ __launch_bounds__(256, 1)
void flash_attn(const float* __restrict__ mask)
{
    extern __shared__ __align__(16) char fsm[];
    uint16_t* sQ = (uint16_t*)fsm + FQ;
    uint16_t* sK = (uint16_t*)fsm + FK;
    uint16_t* sV = (uint16_t*)fsm + FV;
    float* maskS = (float*)(fsm + FMASK_BY);

    const int head = blockIdx.y;
    const int b_   = head >> 4;
    const int h_   = head & 15;
    const size_t hbase = (size_t)head * S * HD;
    const float* mrow = mask + (size_t)b_ * S;

    const int tid  = threadIdx.x;
    const int lane = tid & 31;
    const int w    = tid >> 5;
    const int bq   = blockIdx.x * 128;

    const int lr = tid >> 1;
    const int lk = (tid & 1) * 32;

    {
        const uint4* qg = (const uint4*)(g_qb + hbase + (size_t)(bq + lr) * HD + lk);
        uint4* dq = (uint4*)&sQ[lr * FROW + lk];
#pragma unroll
        for (int q = 0; q < 4; q++) dq[q] = qg[q];
    }
    __syncthreads();

    uint32_t qa[4][4];
    {
        const int ar = w * 16 + (lane & 15);
        const int acb = (lane >> 4) * 8;
#pragma unroll
        for (int kk = 0; kk < 4; kk++)
            ldm_x4(qa[kk], smem_u32(&sQ[ar * FROW + kk * 16 + acb]));
    }

    float acco[8][4];
#pragma unroll
    for (int i = 0; i < 8; i++)
#pragma unroll
        for (int t = 0; t < 4; t++) acco[i][t] = 0.f;
    float m0 = -3.4e38f, m1 = -3.4e38f, l0 = 0.f, l1 = 0.f;

    for (int j = 0; j < S / 128; j++) {
        __syncthreads();
        {
            const size_t off = hbase + (size_t)(j * 128 + lr) * HD + lk;
            const uint4* kg = (const uint4*)(g_kb + off);
            const uint4* vg = (const uint4*)(g_vb + off);
            uint4* dk = (uint4*)&sK[lr * FROW + lk];
            uint4* dv = (uint4*)&sV[lr * FROW + lk];
#pragma unroll
            for (int q = 0; q < 4; q++) { dk[q] = kg[q]; dv[q] = vg[q]; }
            if (tid < 128) maskS[tid] = mrow[j * 128 + tid];
        }
        __syncthreads();

        float accs[16][4];
#pragma unroll
        for (int i = 0; i < 16; i++)
#pragma unroll
            for (int t = 0; t < 4; t++) accs[i][t] = 0.f;

        // ---- S = Q K^T with one-deep K-fragment prefetch ----
        const int krow = (lane & 7) + ((lane >> 4) & 1) * 8;
        const int kcb  = ((lane >> 3) & 1) * 8;
#pragma unroll
        for (int kk = 0; kk < 4; kk++) {
            uint32_t kf[4], kf2[4];
            ldm_x4(kf, smem_u32(&sK[krow * FROW + kk * 16 + kcb]));
#pragma unroll
            for (int np = 0; np < 8; np++) {
                if (np < 7)
                    ldm_x4(kf2, smem_u32(&sK[((np + 1) * 16 + krow) * FROW + kk * 16 + kcb]));
                mma_bf16(accs[2*np],   qa[kk], &kf[0]);
                mma_bf16(accs[2*np+1], qa[kk], &kf[2]);
#pragma unroll
                for (int t = 0; t < 4; t++) kf[t] = kf2[t];
            }
        }

        float tmax0 = -3.4e38f, tmax1 = -3.4e38f;
#pragma unroll
        for (int ni = 0; ni < 16; ni++) {
            const int c = ni * 8 + (lane & 3) * 2;
            const float mk0 = maskS[c], mk1 = maskS[c + 1];
            accs[ni][0] = fmaf(accs[ni][0], SCALE, mk0);
            accs[ni][1] = fmaf(accs[ni][1], SCALE, mk1);
            accs[ni][2] = fmaf(accs[ni][2], SCALE, mk0);
            accs[ni][3] = fmaf(accs[ni][3], SCALE, mk1);
            tmax0 = fmaxf(tmax0, fmaxf(accs[ni][0], accs[ni][1]));
            tmax1 = fmaxf(tmax1, fmaxf(accs[ni][2], accs[ni][3]));
        }
        tmax0 = fmaxf(tmax0, __shfl_xor_sync(~0u, tmax0, 1));
        tmax0 = fmaxf(tmax0, __shfl_xor_sync(~0u, tmax0, 2));
        tmax1 = fmaxf(tmax1, __shfl_xor_sync(~0u, tmax1, 1));
        tmax1 = fmaxf(tmax1, __shfl_xor_sync(~0u, tmax1, 2));

        const float mn0 = fmaxf(m0, tmax0);
        const float mn1 = fmaxf(m1, tmax1);
        const float alpha0 = __expf(m0 - mn0);
        const float alpha1 = __expf(m1 - mn1);
        m0 = mn0; m1 = mn1;

        float sum0 = 0.f, sum1 = 0.f;
#pragma unroll
        for (int ni = 0; ni < 16; ni++) {
            accs[ni][0] = __expf(accs[ni][0] - mn0);
            accs[ni][1] = __expf(accs[ni][1] - mn0);
            accs[ni][2] = __expf(accs[ni][2] - mn1);
            accs[ni][3] = __expf(accs[ni][3] - mn1);
            sum0 += accs[ni][0] + accs[ni][1];
            sum1 += accs[ni][2] + accs[ni][3];
        }
        sum0 += __shfl_xor_sync(~0u, sum0, 1);
        sum0 += __shfl_xor_sync(~0u, sum0, 2);
        sum1 += __shfl_xor_sync(~0u, sum1, 1);
        sum1 += __shfl_xor_sync(~0u, sum1, 2);
        l0 = l0 * alpha0 + sum0;
        l1 = l1 * alpha1 + sum1;

#pragma unroll
        for (int ni = 0; ni < 8; ni++) {
            acco[ni][0] *= alpha0; acco[ni][1] *= alpha0;
            acco[ni][2] *= alpha1; acco[ni][3] *= alpha1;
        }

        // ---- O += P V with one-deep V-fragment prefetch ----
#pragma unroll
        for (int kk = 0; kk < 8; kk++) {
            uint32_t ph[4];
            ph[0] = cvt2(accs[2*kk][0],   accs[2*kk][1]);
            ph[1] = cvt2(accs[2*kk][2],   accs[2*kk][3]);
            ph[2] = cvt2(accs[2*kk+1][0], accs[2*kk+1][1]);
            ph[3] = cvt2(accs[2*kk+1][2], accs[2*kk+1][3]);
            const int vrow = kk * 16 + (lane & 7) + ((lane >> 3) & 1) * 8;
            const int vcb  = (lane >> 4) * 8;
            uint32_t vf[4], vf2[4];
            ldm_x4t(vf, smem_u32(&sV[vrow * FROW + vcb]));
#pragma unroll
            for (int np = 0; np < 4; np++) {
                if (np < 3)
                    ldm_x4t(vf2, smem_u32(&sV[vrow * FROW + (np + 1) * 16 + vcb]));
                mma_bf16(acco[2*np],   ph, &vf[0]);
                mma_bf16(acco[2*np+1], ph, &vf[2]);
#pragma unroll
                for (int t = 0; t < 4; t++) vf[t] = vf2[t];
            }
        }
    }

    const float inv0 = 1.f / l0;
    const float inv1 = 1.f / l1;
    const int q0 = bq + w * 16 + (lane >> 2);
#pragma unroll
    for (int ni = 0; ni < 8; ni++) {
        const int d = ni * 8 + (lane & 3) * 2;
        const size_t i0 = ((size_t)(b_ * S + q0)) * H + h_ * HD + d;
        const size_t i1 = ((size_t)(b_ * S + q0 + 8)) * H + h_ * HD + d;
        *(uint32_t*)&g_cb[i0] = cvt2(acco[ni][0] * inv0, acco[ni][1] * inv0);
        *(uint32_t*)&g_cb[i1] = cvt2(acco[ni][2] * inv1, acco[ni][3] * inv1);
    }
}

// ---------------------------------------------------------------------------
// out = LayerNorm(g_proj + hidden) * gamma + beta
// ---------------------------------------------------------------------------
__global__ __launch_bounds__(256, 1)
void add_ln(const float* __restrict__ hidden,
            const float* __restrict__ gamma,
            const float* __restrict__ beta,
            float* __restrict__ out)
{
    const size_t row = blockIdx.x;
    const int tid = threadIdx.x;
    __shared__ float r1[8], r2[8];

    float4 a  = *(const float4*)&g_proj[row * H + tid * 4];
    float4 hv = *(const float4*)&hidden[row * H + tid * 4];
    float x0 = a.x + hv.x, x1 = a.y + hv.y, x2 = a.z + hv.z, x3 = a.w + hv.w;

    float s1 = x0 + x1 + x2 + x3;
    float s2 = fmaf(x0, x0, fmaf(x1, x1, fmaf(x2, x2, x3 * x3)));
#pragma unroll
    for (int o = 16; o; o >>= 1) {
        s1 += __shfl_xor_sync(~0u, s1, o);
        s2 += __shfl_xor_sync(~0u, s2, o);
    }
    if ((tid & 31) == 0) { r1[tid >> 5] = s1; r2[tid >> 5] = s2; }
    __syncthreads();
    float t1 = 0.f, t2 = 0.f;
#pragma unroll
    for (int i = 0; i < 8; i++) { t1 += r1[i]; t2 += r2[i]; }

    const float mu  = t1 * (1.f / H);
    const float var = t2 * (1.f / H) - mu * mu;
    const float inv = rsqrtf(var + LN_EPS);

    float4 g  = *(const float4*)&gamma[tid * 4];
    float4 bt = *(const float4*)&beta[tid * 4];
    float4 o;
    o.x = (x0 - mu) * inv * g.x + bt.x;
    o.y = (x1 - mu) * inv * g.y + bt.y;
    o.z = (x2 - mu) * inv * g.z + bt.z;
    o.w = (x3 - mu) * inv * g.w + bt.w;
    *(float4*)&out[row * H + tid * 4] = o;
}

// ---------------------------------------------------------------------------
extern "C" void kernel_launch(void* const* d_in, const int* in_sizes, int n_in,
                              void* d_out, int out_size)
{
    const float* hidden = (const float*)d_in[0];
    const float* mask   = (const float*)d_in[1];
    const float* Wq     = (const float*)d_in[2];
    const float* bq     = (const float*)d_in[3];
    const float* Wk     = (const float*)d_in[4];
    const float* bk     = (const float*)d_in[5];
    const float* Wv     = (const float*)d_in[6];
    const float* bv     = (const float*)d_in[7];
    const float* Wo     = (const float*)d_in[8];
    const float* bo     = (const float*)d_in[9];
    const float* gamma  = (const float*)d_in[10];
    const float* beta   = (const float*)d_in[11];
    float* out          = (float*)d_out;

    cudaFuncSetAttribute(gemm_bf16s, cudaFuncAttributeMaxDynamicSharedMemorySize,
                         GEMM_SMEM);
    cudaFuncSetAttribute(flash_attn, cudaFuncAttributeMaxDynamicSharedMemorySize,
                         FLASH_SMEM);

    dim3 blk(256);
    cvt_all<<<((size_t)M * H + 4u * H * H) / 1024, blk>>>(hidden, Wq, Wk, Wv, Wo);

    dim3 gqkv(H / 256, M / 128, 3);     // (4, 64, 3) fused QKV
    gemm_bf16s<<<gqkv, blk, GEMM_SMEM>>>(bq, bk, bv, -1);

    dim3 gfa(S / 128, BH);
    flash_attn<<<gfa, blk, FLASH_SMEM>>>(mask);

    dim3 gproj(H / 256, M / 128);       // (4, 64)
    gemm_bf16s<<<gproj, blk, GEMM_SMEM>>>(bo, bo, bo, 3);

    add_ln<<<M, blk>>>(hidden, gamma, beta, out);
}